// round 8
// baseline (speedup 1.0000x reference)
#include <cuda_runtime.h>
#include <cstddef>

#define N_NODES 100000
#define N_EDGES 3200000
#define D_IN    128
#define D_HID   128
#define D_OUT   64
#define NBLK    391           // ceil(N_NODES / 256)

// ---------------- scratch (no allocation allowed) ----------------
__device__ __align__(16) float g_t   [(size_t)N_NODES * D_OUT];  // h @ W_l2^T
__device__ __align__(16) float g_r   [(size_t)N_NODES * D_OUT];  // h @ W_r2^T + b2
__device__ __align__(16) float g_h   [(size_t)N_NODES * D_HID];  // fallback h storage
__device__ int  g_deg [N_NODES];
__device__ int  g_off [N_NODES + 1];
__device__ int  g_pos [N_NODES];
__device__ int  g_bsum[NBLK];
__device__ int  g_bpre[NBLK];
__device__ __align__(16) int2 g_edge[N_EDGES];                   // (src, w-bits), dst-grouped
__device__ int  g_idx64;   // 1 if edge_index is int64, 0 if int32

// ---------------- f32x2 helpers ----------------
__device__ __forceinline__ unsigned long long ffma2(unsigned long long a,
                                                    unsigned long long b,
                                                    unsigned long long c) {
    unsigned long long d;
    asm("fma.rn.f32x2 %0, %1, %2, %3;" : "=l"(d) : "l"(a), "l"(b), "l"(c));
    return d;
}
__device__ __forceinline__ void unpack2(unsigned long long d, float& lo, float& hi) {
    asm("mov.b64 {%0, %1}, %2;" : "=f"(lo), "=f"(hi) : "l"(d));
}

// Load edge endpoint #e (src if half==0, dst if half==1) honoring detected dtype.
__device__ __forceinline__ int load_idx(const void* ei, int e, int half, int mode64) {
    if (mode64) {
        long long v = __ldg(reinterpret_cast<const long long*>(ei) +
                            (size_t)half * N_EDGES + e);
        return (int)v;
    } else {
        return __ldg(reinterpret_cast<const int*>(ei) + (size_t)half * N_EDGES + e);
    }
}

// ---------------- dtype detection + zero deg (merged) ----------------
__global__ void detect_zero_kernel(const int* __restrict__ ei_words) {
    int i = blockIdx.x * 256 + threadIdx.x;
    if (i < N_NODES) g_deg[i] = 0;
    if (blockIdx.x == 0) {
        __shared__ int any_nonzero;
        if (threadIdx.x == 0) any_nonzero = 0;
        __syncthreads();
        int acc = 0;
        for (int k = threadIdx.x; k < 4096; k += 256)
            acc |= ei_words[2 * k + 1];
        if (acc) atomicOr(&any_nonzero, 1);
        __syncthreads();
        if (threadIdx.x == 0) g_idx64 = any_nonzero ? 0 : 1;
    }
}

// ---------------- CSR build ----------------
__global__ void hist_kernel(const void* __restrict__ ei) {
    int e = blockIdx.x * blockDim.x + threadIdx.x;
    if (e >= N_EDGES) return;
    int mode64 = g_idx64;
    int d = load_idx(ei, e, 1, mode64);
    if ((unsigned)d < N_NODES) atomicAdd(&g_deg[d], 1);
}

__global__ void blocksum_kernel() {
    __shared__ int s[256];
    int i = blockIdx.x * 256 + threadIdx.x;
    s[threadIdx.x] = (i < N_NODES) ? g_deg[i] : 0;
    __syncthreads();
    for (int d = 128; d > 0; d >>= 1) {
        if (threadIdx.x < d) s[threadIdx.x] += s[threadIdx.x + d];
        __syncthreads();
    }
    if (threadIdx.x == 0) g_bsum[blockIdx.x] = s[0];
}

__global__ void scan_bsum_kernel() {
    __shared__ int s[512];
    int t = threadIdx.x;
    int v = (t < NBLK) ? g_bsum[t] : 0;
    s[t] = v;
    __syncthreads();
    for (int d = 1; d < 512; d <<= 1) {
        int tmp = (t >= d) ? s[t - d] : 0;
        __syncthreads();
        s[t] += tmp;
        __syncthreads();
    }
    if (t < NBLK) g_bpre[t] = s[t] - v;      // exclusive
    if (t == 511) g_off[N_NODES] = s[511];   // total
}

__global__ void offsets_kernel() {
    __shared__ int s[256];
    int t = threadIdx.x;
    int i = blockIdx.x * 256 + t;
    int v = (i < N_NODES) ? g_deg[i] : 0;
    s[t] = v;
    __syncthreads();
    for (int d = 1; d < 256; d <<= 1) {
        int tmp = (t >= d) ? s[t - d] : 0;
        __syncthreads();
        s[t] += tmp;
        __syncthreads();
    }
    if (i < N_NODES) {
        int off = g_bpre[blockIdx.x] + s[t] - v;   // exclusive
        g_off[i] = off;
        g_pos[i] = off;
    }
}

__global__ void fill_kernel(const void* __restrict__ ei,
                            const float* __restrict__ ew) {
    int e = blockIdx.x * blockDim.x + threadIdx.x;
    if (e >= N_EDGES) return;
    int mode64 = g_idx64;
    int s = load_idx(ei, e, 0, mode64);
    int d = load_idx(ei, e, 1, mode64);
    if ((unsigned)s >= N_NODES || (unsigned)d >= N_NODES) return;
    int p = atomicAdd(&g_pos[d], 1);
    g_edge[p] = make_int2(s, __float_as_int(__ldg(&ew[e])));
}

// ---------------- fused gather1 + layer1 ------------------------------------------
// 512 threads: warps 0-7 produce (CSR gather-mean + x-row copy into smem tile),
// warps 8-15 consume (f32x2 GEMM h = relu(agg@Wl^T + b + x@Wr^T)).
// Double-buffered 32-node tiles; one __syncthreads per tile swap.
#define F1_WPAD 132
#define F1_TILE 32
#define F1_SMEM_BYTES (2 * 128 * F1_WPAD * 4 + 2 * 2 * F1_TILE * 128 * 4)  // 200704
__global__ void fused1_kernel(const float* __restrict__ x,
                              const float* __restrict__ Wl,
                              const float* __restrict__ bl,
                              const float* __restrict__ Wr,
                              float* __restrict__ hout) {
    extern __shared__ float sm[];
    float* wl = sm;                             // [128][132] native [j][k]
    float* wr = sm + 128 * F1_WPAD;
    float* fbuf = sm + 2 * 128 * F1_WPAD;       // [2 buf][fa 32*128 | fx 32*128]
    const int BUFSZ = 2 * F1_TILE * 128;        // floats per buffer (fa+fx)
    int t = threadIdx.x;
    for (int i = t; i < 128 * 128; i += 512) {
        int j = i >> 7, k = i & 127;
        wl[j * F1_WPAD + k] = Wl[i];
        wr[j * F1_WPAD + k] = Wr[i];
    }
    int wid = t >> 5, lane = t & 31;
    const int NT = N_NODES / F1_TILE;           // 3125, exact
    const int G = gridDim.x;
    __syncthreads();                            // weights ready

    if (wid < 8) {
        // ---------------- producer ----------------
        // prologue: fill buffer 0 with first tile
        int bsel = 0;
        for (int phase = 0; ; ++phase) {
            // phase p fills tile index: blockIdx.x + phase*G  into buffer (phase&1)
            int tile = blockIdx.x + phase * G;
            if (tile < NT) {
                float* fab = fbuf + (phase & 1) * BUFSZ;
                float* fxb = fab + F1_TILE * 128;
                int base = tile * F1_TILE;
                #pragma unroll
                for (int mm = 0; mm < 4; ++mm) {
                    int m = wid * 4 + mm;
                    int node = base + m;
                    float4 xv = __ldg(reinterpret_cast<const float4*>(x + (size_t)node * 128) + lane);
                    *reinterpret_cast<float4*>(&fxb[m * 128 + lane * 4]) = xv;
                    int off = g_off[node], end = g_off[node + 1];
                    float4 a0 = make_float4(0.f, 0.f, 0.f, 0.f);
                    float4 a1 = a0, a2 = a0, a3 = a0;
                    int i = off;
                    for (; i + 4 <= end; i += 4) {
                        int2 e0 = __ldg(reinterpret_cast<const int2*>(g_edge) + i + 0);
                        int2 e1 = __ldg(reinterpret_cast<const int2*>(g_edge) + i + 1);
                        int2 e2 = __ldg(reinterpret_cast<const int2*>(g_edge) + i + 2);
                        int2 e3 = __ldg(reinterpret_cast<const int2*>(g_edge) + i + 3);
                        float4 v0 = __ldg(reinterpret_cast<const float4*>(x + (size_t)e0.x * 128) + lane);
                        float4 v1 = __ldg(reinterpret_cast<const float4*>(x + (size_t)e1.x * 128) + lane);
                        float4 v2 = __ldg(reinterpret_cast<const float4*>(x + (size_t)e2.x * 128) + lane);
                        float4 v3 = __ldg(reinterpret_cast<const float4*>(x + (size_t)e3.x * 128) + lane);
                        float w0 = __int_as_float(e0.y), w1 = __int_as_float(e1.y);
                        float w2 = __int_as_float(e2.y), w3 = __int_as_float(e3.y);
                        a0.x = fmaf(v0.x, w0, a0.x); a0.y = fmaf(v0.y, w0, a0.y);
                        a0.z = fmaf(v0.z, w0, a0.z); a0.w = fmaf(v0.w, w0, a0.w);
                        a1.x = fmaf(v1.x, w1, a1.x); a1.y = fmaf(v1.y, w1, a1.y);
                        a1.z = fmaf(v1.z, w1, a1.z); a1.w = fmaf(v1.w, w1, a1.w);
                        a2.x = fmaf(v2.x, w2, a2.x); a2.y = fmaf(v2.y, w2, a2.y);
                        a2.z = fmaf(v2.z, w2, a2.z); a2.w = fmaf(v2.w, w2, a2.w);
                        a3.x = fmaf(v3.x, w3, a3.x); a3.y = fmaf(v3.y, w3, a3.y);
                        a3.z = fmaf(v3.z, w3, a3.z); a3.w = fmaf(v3.w, w3, a3.w);
                    }
                    for (; i < end; ++i) {
                        int2 e = __ldg(reinterpret_cast<const int2*>(g_edge) + i);
                        float w = __int_as_float(e.y);
                        float4 v = __ldg(reinterpret_cast<const float4*>(x + (size_t)e.x * 128) + lane);
                        a0.x = fmaf(v.x, w, a0.x); a0.y = fmaf(v.y, w, a0.y);
                        a0.z = fmaf(v.z, w, a0.z); a0.w = fmaf(v.w, w, a0.w);
                    }
                    a0.x += (a1.x + a2.x) + a3.x;
                    a0.y += (a1.y + a2.y) + a3.y;
                    a0.z += (a1.z + a2.z) + a3.z;
                    a0.w += (a1.w + a2.w) + a3.w;
                    float inv = 1.0f / fmaxf((float)(end - off), 1.0f);
                    a0.x *= inv; a0.y *= inv; a0.z *= inv; a0.w *= inv;
                    *reinterpret_cast<float4*>(&fab[m * 128 + lane * 4]) = a0;
                }
            }
            __syncthreads();                    // handoff to consumers
            // consumers are processing tile blockIdx.x + (phase)*G ... loop exit:
            if (blockIdx.x + phase * G >= NT) break;   // consumer just did last tile? see below
            (void)bsel;
        }
    } else {
        // ---------------- consumer ----------------
        int tc = t - 256;
        int j = tc & 63;                        // channels j, j+64
        int grp = tc >> 6;                      // nodes grp*8 .. grp*8+7
        float bj0 = __ldg(&bl[j]), bj1 = __ldg(&bl[j + 64]);
        const float* wl0 = wl + j * F1_WPAD;
        const float* wl1 = wl + (j + 64) * F1_WPAD;
        const float* wr0 = wr + j * F1_WPAD;
        const float* wr1 = wr + (j + 64) * F1_WPAD;
        for (int phase = 0; ; ++phase) {
            __syncthreads();                    // wait for producer fill of buffer (phase&1)
            int tile = blockIdx.x + phase * G;
            if (tile >= NT) break;
            const float* fab = fbuf + (phase & 1) * BUFSZ;
            const float* fxb = fab + F1_TILE * 128;
            int base = tile * F1_TILE;
            unsigned long long acc0[8], acc1[8];
            #pragma unroll
            for (int n = 0; n < 8; ++n) { acc0[n] = 0ull; acc1[n] = 0ull; }
            const float* fan = fab + grp * 8 * 128;
            const float* fxn = fxb + grp * 8 * 128;
            #pragma unroll 4
            for (int k = 0; k < 128; k += 4) {
                ulonglong2 wla = *reinterpret_cast<const ulonglong2*>(wl0 + k);
                ulonglong2 wlb = *reinterpret_cast<const ulonglong2*>(wl1 + k);
                ulonglong2 wra = *reinterpret_cast<const ulonglong2*>(wr0 + k);
                ulonglong2 wrb = *reinterpret_cast<const ulonglong2*>(wr1 + k);
                #pragma unroll
                for (int n = 0; n < 8; ++n) {
                    ulonglong2 f_a = *reinterpret_cast<const ulonglong2*>(fan + n * 128 + k);
                    ulonglong2 f_x = *reinterpret_cast<const ulonglong2*>(fxn + n * 128 + k);
                    acc0[n] = ffma2(wla.x, f_a.x, acc0[n]);
                    acc0[n] = ffma2(wla.y, f_a.y, acc0[n]);
                    acc0[n] = ffma2(wra.x, f_x.x, acc0[n]);
                    acc0[n] = ffma2(wra.y, f_x.y, acc0[n]);
                    acc1[n] = ffma2(wlb.x, f_a.x, acc1[n]);
                    acc1[n] = ffma2(wlb.y, f_a.y, acc1[n]);
                    acc1[n] = ffma2(wrb.x, f_x.x, acc1[n]);
                    acc1[n] = ffma2(wrb.y, f_x.y, acc1[n]);
                }
            }
            #pragma unroll
            for (int n = 0; n < 8; ++n) {
                int node = base + grp * 8 + n;
                float lo, hi;
                unpack2(acc0[n], lo, hi);
                hout[(size_t)node * 128 + j] = fmaxf(lo + hi + bj0, 0.f);
                unpack2(acc1[n], lo, hi);
                hout[(size_t)node * 128 + j + 64] = fmaxf(lo + hi + bj1, 0.f);
            }
        }
    }
}

// ---------------- tmat2 (f32x2, K-packed, fused): t = h@Wl2^T ; r = h@Wr2^T + b2 --------
#define T2_WPAD 132
#define T2_TILE 32
#define T2_SMEM_BYTES (2 * 64 * T2_WPAD * 4 + T2_TILE * 128 * 4)  // 83968
__global__ void tmat2_kernel(const float* __restrict__ h,
                             const float* __restrict__ Wl2,
                             const float* __restrict__ Wr2,
                             const float* __restrict__ b2) {
    extern __shared__ float sm[];
    float* wl = sm;                             // [64][132] native [j][k]
    float* wr = sm + 64 * T2_WPAD;
    float* fh = sm + 2 * 64 * T2_WPAD;          // [32][128]
    int t = threadIdx.x;
    for (int i = t; i < 64 * 128; i += 512) {
        int j = i >> 7, k = i & 127;
        wl[j * T2_WPAD + k] = Wl2[i];
        wr[j * T2_WPAD + k] = Wr2[i];
    }
    int j = t & 63;
    int grp = t >> 6;                           // 0..7 -> nodes grp*4 .. grp*4+3
    float bj = b2[j];
    __syncthreads();
    const int NT = N_NODES / T2_TILE;           // 3125
    for (int tile = blockIdx.x; tile < NT; tile += gridDim.x) {
        int base = tile * T2_TILE;
        __syncthreads();
        for (int i = t; i < T2_TILE * 128; i += 512)
            fh[i] = h[(size_t)base * 128 + i];
        __syncthreads();
        unsigned long long tac[4], rac[4];
        #pragma unroll
        for (int n = 0; n < 4; ++n) { tac[n] = 0ull; rac[n] = 0ull; }
        const float* fn = fh + grp * 4 * 128;
        const float* wlj = wl + j * T2_WPAD;
        const float* wrj = wr + j * T2_WPAD;
        #pragma unroll 4
        for (int k = 0; k < 128; k += 4) {
            ulonglong2 w_l = *reinterpret_cast<const ulonglong2*>(wlj + k);
            ulonglong2 w_r = *reinterpret_cast<const ulonglong2*>(wrj + k);
            #pragma unroll
            for (int n = 0; n < 4; ++n) {
                ulonglong2 f = *reinterpret_cast<const ulonglong2*>(fn + n * 128 + k);
                tac[n] = ffma2(w_l.x, f.x, tac[n]);
                tac[n] = ffma2(w_l.y, f.y, tac[n]);
                rac[n] = ffma2(w_r.x, f.x, rac[n]);
                rac[n] = ffma2(w_r.y, f.y, rac[n]);
            }
        }
        #pragma unroll
        for (int n = 0; n < 4; ++n) {
            int node = base + grp * 4 + n;
            float lo, hi;
            unpack2(tac[n], lo, hi);
            g_t[(size_t)node * 64 + j] = lo + hi;
            unpack2(rac[n], lo, hi);
            g_r[(size_t)node * 64 + j] = lo + hi + bj;
        }
    }
}

// ---------------- gather2 + epilogue: out = mean-agg(t) + r ----------------
// HALF-warp per node (16 lanes x float4 = 64 ch); 4-way unrolled
__global__ void gather2_kernel(float* __restrict__ out) {
    int gt = blockIdx.x * blockDim.x + threadIdx.x;
    int n = gt >> 4;
    if (n >= N_NODES) return;
    int sub = gt & 15;
    int off = g_off[n], end = g_off[n + 1];
    float4 a0 = make_float4(0.f, 0.f, 0.f, 0.f);
    float4 a1 = a0, a2 = a0, a3 = a0;
    int i = off;
    for (; i + 4 <= end; i += 4) {
        int2 e0 = __ldg(reinterpret_cast<const int2*>(g_edge) + i + 0);
        int2 e1 = __ldg(reinterpret_cast<const int2*>(g_edge) + i + 1);
        int2 e2 = __ldg(reinterpret_cast<const int2*>(g_edge) + i + 2);
        int2 e3 = __ldg(reinterpret_cast<const int2*>(g_edge) + i + 3);
        float4 v0 = __ldg(reinterpret_cast<const float4*>(g_t + (size_t)e0.x * D_OUT) + sub);
        float4 v1 = __ldg(reinterpret_cast<const float4*>(g_t + (size_t)e1.x * D_OUT) + sub);
        float4 v2 = __ldg(reinterpret_cast<const float4*>(g_t + (size_t)e2.x * D_OUT) + sub);
        float4 v3 = __ldg(reinterpret_cast<const float4*>(g_t + (size_t)e3.x * D_OUT) + sub);
        float w0 = __int_as_float(e0.y), w1 = __int_as_float(e1.y);
        float w2 = __int_as_float(e2.y), w3 = __int_as_float(e3.y);
        a0.x = fmaf(v0.x, w0, a0.x); a0.y = fmaf(v0.y, w0, a0.y);
        a0.z = fmaf(v0.z, w0, a0.z); a0.w = fmaf(v0.w, w0, a0.w);
        a1.x = fmaf(v1.x, w1, a1.x); a1.y = fmaf(v1.y, w1, a1.y);
        a1.z = fmaf(v1.z, w1, a1.z); a1.w = fmaf(v1.w, w1, a1.w);
        a2.x = fmaf(v2.x, w2, a2.x); a2.y = fmaf(v2.y, w2, a2.y);
        a2.z = fmaf(v2.z, w2, a2.z); a2.w = fmaf(v2.w, w2, a2.w);
        a3.x = fmaf(v3.x, w3, a3.x); a3.y = fmaf(v3.y, w3, a3.y);
        a3.z = fmaf(v3.z, w3, a3.z); a3.w = fmaf(v3.w, w3, a3.w);
    }
    for (; i < end; ++i) {
        int2 e = __ldg(reinterpret_cast<const int2*>(g_edge) + i);
        float w = __int_as_float(e.y);
        float4 v = __ldg(reinterpret_cast<const float4*>(g_t + (size_t)e.x * D_OUT) + sub);
        a0.x = fmaf(v.x, w, a0.x); a0.y = fmaf(v.y, w, a0.y);
        a0.z = fmaf(v.z, w, a0.z); a0.w = fmaf(v.w, w, a0.w);
    }
    a0.x += (a1.x + a2.x) + a3.x;
    a0.y += (a1.y + a2.y) + a3.y;
    a0.z += (a1.z + a2.z) + a3.z;
    a0.w += (a1.w + a2.w) + a3.w;
    float inv = 1.0f / fmaxf((float)(end - off), 1.0f);
    float4 rv = __ldg(reinterpret_cast<const float4*>(g_r + (size_t)n * D_OUT) + sub);
    a0.x = fmaf(a0.x, inv, rv.x);
    a0.y = fmaf(a0.y, inv, rv.y);
    a0.z = fmaf(a0.z, inv, rv.z);
    a0.w = fmaf(a0.w, inv, rv.w);
    reinterpret_cast<float4*>(out + (size_t)n * D_OUT)[sub] = a0;
}

// ---------------- launch ----------------
extern "C" void kernel_launch(void* const* d_in, const int* in_sizes, int n_in,
                              void* d_out, int out_size) {
    (void)in_sizes; (void)n_in;
    const float* x   = (const float*)d_in[0];
    const void*  ei  = d_in[1];                 // int32 or int64, detected on device
    const float* ew  = (const float*)d_in[2];
    const float* Wl1 = (const float*)d_in[3];
    const float* bl1 = (const float*)d_in[4];
    const float* Wr1 = (const float*)d_in[5];
    const float* Wl2 = (const float*)d_in[6];
    const float* bl2 = (const float*)d_in[7];
    const float* Wr2 = (const float*)d_in[8];

    float* hptr;
    float* lptr;
    const size_t full = (size_t)N_NODES * (D_HID + D_OUT);
    if ((size_t)out_size >= full) {
        hptr = (float*)d_out;
        lptr = hptr + (size_t)N_NODES * D_HID;
    } else {
        void* sym = nullptr;
        cudaGetSymbolAddress(&sym, g_h);
        hptr = (float*)sym;
        lptr = (float*)d_out;
    }

    int smcount = 148;
    if (cudaDeviceGetAttribute(&smcount, cudaDevAttrMultiProcessorCount, 0) != cudaSuccess)
        smcount = 148;

    cudaFuncSetAttribute(fused1_kernel,
                         cudaFuncAttributeMaxDynamicSharedMemorySize, F1_SMEM_BYTES);
    cudaFuncSetAttribute(tmat2_kernel,
                         cudaFuncAttributeMaxDynamicSharedMemorySize, T2_SMEM_BYTES);

    detect_zero_kernel<<<NBLK, 256>>>((const int*)ei);
    hist_kernel<<<N_EDGES / 256, 256>>>(ei);
    blocksum_kernel<<<NBLK, 256>>>();
    scan_bsum_kernel<<<1, 512>>>();
    offsets_kernel<<<NBLK, 256>>>();
    fill_kernel<<<N_EDGES / 256, 256>>>(ei, ew);
    fused1_kernel<<<smcount, 512, F1_SMEM_BYTES>>>(x, Wl1, bl1, Wr1, hptr);
    tmat2_kernel<<<2 * smcount, 512, T2_SMEM_BYTES>>>(hptr, Wl2, Wr2, bl2);
    gather2_kernel<<<(N_NODES * 16 + 255) / 256, 256>>>(lptr);
}

// round 9
// speedup vs baseline: 1.0387x; 1.0387x over previous
#include <cuda_runtime.h>
#include <cuda_bf16.h>
#include <cstddef>

#define N_NODES 100000
#define N_EDGES 3200000
#define D_IN    128
#define D_HID   128
#define D_OUT   64
#define NBLK    391           // ceil(N_NODES / 256)

// ---------------- scratch (no allocation allowed) ----------------
__device__ __align__(16) float g_agg1[(size_t)N_NODES * D_IN];       // mean-agg of x (fp32)
__device__ __align__(16) __nv_bfloat16 g_xb[(size_t)N_NODES * D_IN]; // x in bf16 (gather copy)
__device__ __align__(16) __nv_bfloat16 g_t [(size_t)N_NODES * D_OUT];// h @ W_l2^T (bf16 gather copy)
__device__ __align__(16) float g_r   [(size_t)N_NODES * D_OUT];      // h @ W_r2^T + b2 (fp32)
__device__ __align__(16) float g_h   [(size_t)N_NODES * D_HID];      // fallback h storage
__device__ int  g_deg [N_NODES];
__device__ int  g_off [N_NODES + 1];
__device__ int  g_pos [N_NODES];
__device__ int  g_bsum[NBLK];
__device__ int  g_bpre[NBLK];
__device__ __align__(16) int2 g_edge[N_EDGES];                       // (src, w-bits), dst-grouped
__device__ int  g_idx64;   // 1 if edge_index is int64, 0 if int32

// ---------------- f32x2 helpers ----------------
__device__ __forceinline__ unsigned long long ffma2(unsigned long long a,
                                                    unsigned long long b,
                                                    unsigned long long c) {
    unsigned long long d;
    asm("fma.rn.f32x2 %0, %1, %2, %3;" : "=l"(d) : "l"(a), "l"(b), "l"(c));
    return d;
}
__device__ __forceinline__ void unpack2(unsigned long long d, float& lo, float& hi) {
    asm("mov.b64 {%0, %1}, %2;" : "=f"(lo), "=f"(hi) : "l"(d));
}

// load 4 bf16 (8 bytes) -> float4
__device__ __forceinline__ float4 ld_bf4(const __nv_bfloat16* base, int sub) {
    uint2 u = __ldg(reinterpret_cast<const uint2*>(base) + sub);
    __nv_bfloat162 p0 = *reinterpret_cast<__nv_bfloat162*>(&u.x);
    __nv_bfloat162 p1 = *reinterpret_cast<__nv_bfloat162*>(&u.y);
    float2 f0 = __bfloat1622float2(p0);
    float2 f1 = __bfloat1622float2(p1);
    return make_float4(f0.x, f0.y, f1.x, f1.y);
}

// Load edge endpoint #e (src if half==0, dst if half==1) honoring detected dtype.
__device__ __forceinline__ int load_idx(const void* ei, int e, int half, int mode64) {
    if (mode64) {
        long long v = __ldg(reinterpret_cast<const long long*>(ei) +
                            (size_t)half * N_EDGES + e);
        return (int)v;
    } else {
        return __ldg(reinterpret_cast<const int*>(ei) + (size_t)half * N_EDGES + e);
    }
}

// ---------------- dtype detection + zero deg (merged) ----------------
__global__ void detect_zero_kernel(const int* __restrict__ ei_words) {
    int i = blockIdx.x * 256 + threadIdx.x;
    if (i < N_NODES) g_deg[i] = 0;
    if (blockIdx.x == 0) {
        __shared__ int any_nonzero;
        if (threadIdx.x == 0) any_nonzero = 0;
        __syncthreads();
        int acc = 0;
        for (int k = threadIdx.x; k < 4096; k += 256)
            acc |= ei_words[2 * k + 1];
        if (acc) atomicOr(&any_nonzero, 1);
        __syncthreads();
        if (threadIdx.x == 0) g_idx64 = any_nonzero ? 0 : 1;
    }
}

// ---------------- x -> bf16 copy ----------------
__global__ void xcvt_kernel(const float* __restrict__ x) {
    size_t i = (size_t)blockIdx.x * blockDim.x + threadIdx.x;
    size_t stride = (size_t)gridDim.x * blockDim.x;
    const size_t NPAIR = (size_t)N_NODES * D_IN / 2;
    for (size_t k = i; k < NPAIR; k += stride) {
        float2 v = reinterpret_cast<const float2*>(x)[k];
        reinterpret_cast<__nv_bfloat162*>(g_xb)[k] = __float22bfloat162_rn(v);
    }
}

// ---------------- CSR build ----------------
__global__ void hist_kernel(const void* __restrict__ ei) {
    int e = blockIdx.x * blockDim.x + threadIdx.x;
    if (e >= N_EDGES) return;
    int mode64 = g_idx64;
    int d = load_idx(ei, e, 1, mode64);
    if ((unsigned)d < N_NODES) atomicAdd(&g_deg[d], 1);
}

__global__ void blocksum_kernel() {
    __shared__ int s[256];
    int i = blockIdx.x * 256 + threadIdx.x;
    s[threadIdx.x] = (i < N_NODES) ? g_deg[i] : 0;
    __syncthreads();
    for (int d = 128; d > 0; d >>= 1) {
        if (threadIdx.x < d) s[threadIdx.x] += s[threadIdx.x + d];
        __syncthreads();
    }
    if (threadIdx.x == 0) g_bsum[blockIdx.x] = s[0];
}

__global__ void scan_bsum_kernel() {
    __shared__ int s[512];
    int t = threadIdx.x;
    int v = (t < NBLK) ? g_bsum[t] : 0;
    s[t] = v;
    __syncthreads();
    for (int d = 1; d < 512; d <<= 1) {
        int tmp = (t >= d) ? s[t - d] : 0;
        __syncthreads();
        s[t] += tmp;
        __syncthreads();
    }
    if (t < NBLK) g_bpre[t] = s[t] - v;      // exclusive
    if (t == 511) g_off[N_NODES] = s[511];   // total
}

__global__ void offsets_kernel() {
    __shared__ int s[256];
    int t = threadIdx.x;
    int i = blockIdx.x * 256 + t;
    int v = (i < N_NODES) ? g_deg[i] : 0;
    s[t] = v;
    __syncthreads();
    for (int d = 1; d < 256; d <<= 1) {
        int tmp = (t >= d) ? s[t - d] : 0;
        __syncthreads();
        s[t] += tmp;
        __syncthreads();
    }
    if (i < N_NODES) {
        int off = g_bpre[blockIdx.x] + s[t] - v;   // exclusive
        g_off[i] = off;
        g_pos[i] = off;
    }
}

__global__ void fill_kernel(const void* __restrict__ ei,
                            const float* __restrict__ ew) {
    int e = blockIdx.x * blockDim.x + threadIdx.x;
    if (e >= N_EDGES) return;
    int mode64 = g_idx64;
    int s = load_idx(ei, e, 0, mode64);
    int d = load_idx(ei, e, 1, mode64);
    if ((unsigned)s >= N_NODES || (unsigned)d >= N_NODES) return;
    int p = atomicAdd(&g_pos[d], 1);
    g_edge[p] = make_int2(s, __float_as_int(__ldg(&ew[e])));
}

// ---------------- gather1 (bf16 src): agg1[n] = mean over in-edges of x[src]*w --------
// one warp per node; lane covers 4 features (8B bf16); 8-way unrolled (MLP=8)
__global__ void gather1_kernel() {
    int n = (blockIdx.x * blockDim.x + threadIdx.x) >> 5;
    if (n >= N_NODES) return;
    int lane = threadIdx.x & 31;
    int off = g_off[n], end = g_off[n + 1];
    float4 a0 = make_float4(0.f, 0.f, 0.f, 0.f);
    float4 a1 = a0, a2 = a0, a3 = a0, a4 = a0, a5 = a0, a6 = a0, a7 = a0;
    int i = off;
    for (; i + 8 <= end; i += 8) {
        int2 e0 = __ldg(reinterpret_cast<const int2*>(g_edge) + i + 0);
        int2 e1 = __ldg(reinterpret_cast<const int2*>(g_edge) + i + 1);
        int2 e2 = __ldg(reinterpret_cast<const int2*>(g_edge) + i + 2);
        int2 e3 = __ldg(reinterpret_cast<const int2*>(g_edge) + i + 3);
        int2 e4 = __ldg(reinterpret_cast<const int2*>(g_edge) + i + 4);
        int2 e5 = __ldg(reinterpret_cast<const int2*>(g_edge) + i + 5);
        int2 e6 = __ldg(reinterpret_cast<const int2*>(g_edge) + i + 6);
        int2 e7 = __ldg(reinterpret_cast<const int2*>(g_edge) + i + 7);
        float4 v0 = ld_bf4(g_xb + (size_t)e0.x * D_IN, lane);
        float4 v1 = ld_bf4(g_xb + (size_t)e1.x * D_IN, lane);
        float4 v2 = ld_bf4(g_xb + (size_t)e2.x * D_IN, lane);
        float4 v3 = ld_bf4(g_xb + (size_t)e3.x * D_IN, lane);
        float4 v4 = ld_bf4(g_xb + (size_t)e4.x * D_IN, lane);
        float4 v5 = ld_bf4(g_xb + (size_t)e5.x * D_IN, lane);
        float4 v6 = ld_bf4(g_xb + (size_t)e6.x * D_IN, lane);
        float4 v7 = ld_bf4(g_xb + (size_t)e7.x * D_IN, lane);
        float w0 = __int_as_float(e0.y), w1 = __int_as_float(e1.y);
        float w2 = __int_as_float(e2.y), w3 = __int_as_float(e3.y);
        float w4 = __int_as_float(e4.y), w5 = __int_as_float(e5.y);
        float w6 = __int_as_float(e6.y), w7 = __int_as_float(e7.y);
        a0.x = fmaf(v0.x, w0, a0.x); a0.y = fmaf(v0.y, w0, a0.y);
        a0.z = fmaf(v0.z, w0, a0.z); a0.w = fmaf(v0.w, w0, a0.w);
        a1.x = fmaf(v1.x, w1, a1.x); a1.y = fmaf(v1.y, w1, a1.y);
        a1.z = fmaf(v1.z, w1, a1.z); a1.w = fmaf(v1.w, w1, a1.w);
        a2.x = fmaf(v2.x, w2, a2.x); a2.y = fmaf(v2.y, w2, a2.y);
        a2.z = fmaf(v2.z, w2, a2.z); a2.w = fmaf(v2.w, w2, a2.w);
        a3.x = fmaf(v3.x, w3, a3.x); a3.y = fmaf(v3.y, w3, a3.y);
        a3.z = fmaf(v3.z, w3, a3.z); a3.w = fmaf(v3.w, w3, a3.w);
        a4.x = fmaf(v4.x, w4, a4.x); a4.y = fmaf(v4.y, w4, a4.y);
        a4.z = fmaf(v4.z, w4, a4.z); a4.w = fmaf(v4.w, w4, a4.w);
        a5.x = fmaf(v5.x, w5, a5.x); a5.y = fmaf(v5.y, w5, a5.y);
        a5.z = fmaf(v5.z, w5, a5.z); a5.w = fmaf(v5.w, w5, a5.w);
        a6.x = fmaf(v6.x, w6, a6.x); a6.y = fmaf(v6.y, w6, a6.y);
        a6.z = fmaf(v6.z, w6, a6.z); a6.w = fmaf(v6.w, w6, a6.w);
        a7.x = fmaf(v7.x, w7, a7.x); a7.y = fmaf(v7.y, w7, a7.y);
        a7.z = fmaf(v7.z, w7, a7.z); a7.w = fmaf(v7.w, w7, a7.w);
    }
    for (; i < end; ++i) {
        int2 e = __ldg(reinterpret_cast<const int2*>(g_edge) + i);
        float w = __int_as_float(e.y);
        float4 v = ld_bf4(g_xb + (size_t)e.x * D_IN, lane);
        a0.x = fmaf(v.x, w, a0.x); a0.y = fmaf(v.y, w, a0.y);
        a0.z = fmaf(v.z, w, a0.z); a0.w = fmaf(v.w, w, a0.w);
    }
    a0.x += (a1.x + a2.x) + (a3.x + a4.x) + (a5.x + a6.x) + a7.x;
    a0.y += (a1.y + a2.y) + (a3.y + a4.y) + (a5.y + a6.y) + a7.y;
    a0.z += (a1.z + a2.z) + (a3.z + a4.z) + (a5.z + a6.z) + a7.z;
    a0.w += (a1.w + a2.w) + (a3.w + a4.w) + (a5.w + a6.w) + a7.w;
    float inv = 1.0f / fmaxf((float)(end - off), 1.0f);
    a0.x *= inv; a0.y *= inv; a0.z *= inv; a0.w *= inv;
    reinterpret_cast<float4*>(g_agg1 + (size_t)n * D_IN)[lane] = a0;
}

// ---------------- layer 1 (f32x2, K-packed, 2ch x 8node blocking) -------------------
#define L1_WPAD 132
#define L1_TILE 64
#define L1_SMEM_BYTES (2 * 128 * L1_WPAD * 4 + 2 * L1_TILE * 128 * 4)  // 200704
__global__ void layer1_kernel(const float* __restrict__ x,
                              const float* __restrict__ Wl,
                              const float* __restrict__ bl,
                              const float* __restrict__ Wr,
                              float* __restrict__ hout) {
    extern __shared__ float sm[];
    float* wl = sm;                             // [128][132] native [j][k]
    float* wr = sm + 128 * L1_WPAD;
    float* fa = sm + 2 * 128 * L1_WPAD;         // [64][128]
    float* fx = fa + L1_TILE * 128;
    int t = threadIdx.x;
    for (int i = t; i < 128 * 128; i += 512) {
        int j = i >> 7, k = i & 127;
        wl[j * L1_WPAD + k] = Wl[i];
        wr[j * L1_WPAD + k] = Wr[i];
    }
    int j = t & 63;                             // channels j, j+64
    int grp = t >> 6;                           // 0..7 -> nodes grp*8 .. grp*8+7
    float bj0 = bl[j], bj1 = bl[j + 64];
    __syncthreads();
    const int NT = (N_NODES + L1_TILE - 1) / L1_TILE;   // 1563 (last tile partial)
    for (int tile = blockIdx.x; tile < NT; tile += gridDim.x) {
        int base = tile * L1_TILE;
        __syncthreads();
        for (int i = t; i < L1_TILE * 128; i += 512) {
            int n = i >> 7, k = i & 127;
            int node = base + n; if (node >= N_NODES) node = N_NODES - 1;
            fa[i] = g_agg1[(size_t)node * 128 + k];
            fx[i] = x[(size_t)node * 128 + k];
        }
        __syncthreads();
        unsigned long long acc0[8], acc1[8];
        #pragma unroll
        for (int n = 0; n < 8; ++n) { acc0[n] = 0ull; acc1[n] = 0ull; }
        const float* fan = fa + grp * 8 * 128;
        const float* fxn = fx + grp * 8 * 128;
        const float* wl0 = wl + j * L1_WPAD;
        const float* wl1 = wl + (j + 64) * L1_WPAD;
        const float* wr0 = wr + j * L1_WPAD;
        const float* wr1 = wr + (j + 64) * L1_WPAD;
        #pragma unroll 4
        for (int k = 0; k < 128; k += 4) {
            ulonglong2 wla = *reinterpret_cast<const ulonglong2*>(wl0 + k);
            ulonglong2 wlb = *reinterpret_cast<const ulonglong2*>(wl1 + k);
            ulonglong2 wra = *reinterpret_cast<const ulonglong2*>(wr0 + k);
            ulonglong2 wrb = *reinterpret_cast<const ulonglong2*>(wr1 + k);
            #pragma unroll
            for (int n = 0; n < 8; ++n) {
                ulonglong2 f_a = *reinterpret_cast<const ulonglong2*>(fan + n * 128 + k);
                ulonglong2 f_x = *reinterpret_cast<const ulonglong2*>(fxn + n * 128 + k);
                acc0[n] = ffma2(wla.x, f_a.x, acc0[n]);
                acc0[n] = ffma2(wla.y, f_a.y, acc0[n]);
                acc0[n] = ffma2(wra.x, f_x.x, acc0[n]);
                acc0[n] = ffma2(wra.y, f_x.y, acc0[n]);
                acc1[n] = ffma2(wlb.x, f_a.x, acc1[n]);
                acc1[n] = ffma2(wlb.y, f_a.y, acc1[n]);
                acc1[n] = ffma2(wrb.x, f_x.x, acc1[n]);
                acc1[n] = ffma2(wrb.y, f_x.y, acc1[n]);
            }
        }
        #pragma unroll
        for (int n = 0; n < 8; ++n) {
            int node = base + grp * 8 + n;
            if (node < N_NODES) {
                float lo, hi;
                unpack2(acc0[n], lo, hi);
                hout[(size_t)node * 128 + j] = fmaxf(lo + hi + bj0, 0.f);
                unpack2(acc1[n], lo, hi);
                hout[(size_t)node * 128 + j + 64] = fmaxf(lo + hi + bj1, 0.f);
            }
        }
    }
}

// ---------------- tmat2 (f32x2, K-packed, fused): t(bf16) = h@Wl2^T ; r = h@Wr2^T + b2 --
#define T2_WPAD 132
#define T2_TILE 32
#define T2_SMEM_BYTES (2 * 64 * T2_WPAD * 4 + T2_TILE * 128 * 4)  // 83968
__global__ void tmat2_kernel(const float* __restrict__ h,
                             const float* __restrict__ Wl2,
                             const float* __restrict__ Wr2,
                             const float* __restrict__ b2) {
    extern __shared__ float sm[];
    float* wl = sm;                             // [64][132] native [j][k]
    float* wr = sm + 64 * T2_WPAD;
    float* fh = sm + 2 * 64 * T2_WPAD;          // [32][128]
    int t = threadIdx.x;
    for (int i = t; i < 64 * 128; i += 512) {
        int j = i >> 7, k = i & 127;
        wl[j * T2_WPAD + k] = Wl2[i];
        wr[j * T2_WPAD + k] = Wr2[i];
    }
    int j = t & 63;
    int grp = t >> 6;                           // 0..7 -> nodes grp*4 .. grp*4+3
    float bj = b2[j];
    __syncthreads();
    const int NT = N_NODES / T2_TILE;           // 3125
    for (int tile = blockIdx.x; tile < NT; tile += gridDim.x) {
        int base = tile * T2_TILE;
        __syncthreads();
        for (int i = t; i < T2_TILE * 128; i += 512)
            fh[i] = h[(size_t)base * 128 + i];
        __syncthreads();
        unsigned long long tac[4], rac[4];
        #pragma unroll
        for (int n = 0; n < 4; ++n) { tac[n] = 0ull; rac[n] = 0ull; }
        const float* fn = fh + grp * 4 * 128;
        const float* wlj = wl + j * T2_WPAD;
        const float* wrj = wr + j * T2_WPAD;
        #pragma unroll 4
        for (int k = 0; k < 128; k += 4) {
            ulonglong2 w_l = *reinterpret_cast<const ulonglong2*>(wlj + k);
            ulonglong2 w_r = *reinterpret_cast<const ulonglong2*>(wrj + k);
            #pragma unroll
            for (int n = 0; n < 4; ++n) {
                ulonglong2 f = *reinterpret_cast<const ulonglong2*>(fn + n * 128 + k);
                tac[n] = ffma2(w_l.x, f.x, tac[n]);
                tac[n] = ffma2(w_l.y, f.y, tac[n]);
                rac[n] = ffma2(w_r.x, f.x, rac[n]);
                rac[n] = ffma2(w_r.y, f.y, rac[n]);
            }
        }
        #pragma unroll
        for (int n = 0; n < 4; ++n) {
            int node = base + grp * 4 + n;
            float lo, hi;
            unpack2(tac[n], lo, hi);
            g_t[(size_t)node * 64 + j] = __float2bfloat16(lo + hi);
            unpack2(rac[n], lo, hi);
            g_r[(size_t)node * 64 + j] = lo + hi + bj;
        }
    }
}

// ---------------- gather2 + epilogue: out = mean-agg(t) + r (bf16 t) ----------------
// HALF-warp per node (16 lanes x 4 features); 4-way unrolled
__global__ void gather2_kernel(float* __restrict__ out) {
    int gt = blockIdx.x * blockDim.x + threadIdx.x;
    int n = gt >> 4;
    if (n >= N_NODES) return;
    int sub = gt & 15;
    int off = g_off[n], end = g_off[n + 1];
    float4 a0 = make_float4(0.f, 0.f, 0.f, 0.f);
    float4 a1 = a0, a2 = a0, a3 = a0;
    int i = off;
    for (; i + 4 <= end; i += 4) {
        int2 e0 = __ldg(reinterpret_cast<const int2*>(g_edge) + i + 0);
        int2 e1 = __ldg(reinterpret_cast<const int2*>(g_edge) + i + 1);
        int2 e2 = __ldg(reinterpret_cast<const int2*>(g_edge) + i + 2);
        int2 e3 = __ldg(reinterpret_cast<const int2*>(g_edge) + i + 3);
        float4 v0 = ld_bf4(g_t + (size_t)e0.x * D_OUT, sub);
        float4 v1 = ld_bf4(g_t + (size_t)e1.x * D_OUT, sub);
        float4 v2 = ld_bf4(g_t + (size_t)e2.x * D_OUT, sub);
        float4 v3 = ld_bf4(g_t + (size_t)e3.x * D_OUT, sub);
        float w0 = __int_as_float(e0.y), w1 = __int_as_float(e1.y);
        float w2 = __int_as_float(e2.y), w3 = __int_as_float(e3.y);
        a0.x = fmaf(v0.x, w0, a0.x); a0.y = fmaf(v0.y, w0, a0.y);
        a0.z = fmaf(v0.z, w0, a0.z); a0.w = fmaf(v0.w, w0, a0.w);
        a1.x = fmaf(v1.x, w1, a1.x); a1.y = fmaf(v1.y, w1, a1.y);
        a1.z = fmaf(v1.z, w1, a1.z); a1.w = fmaf(v1.w, w1, a1.w);
        a2.x = fmaf(v2.x, w2, a2.x); a2.y = fmaf(v2.y, w2, a2.y);
        a2.z = fmaf(v2.z, w2, a2.z); a2.w = fmaf(v2.w, w2, a2.w);
        a3.x = fmaf(v3.x, w3, a3.x); a3.y = fmaf(v3.y, w3, a3.y);
        a3.z = fmaf(v3.z, w3, a3.z); a3.w = fmaf(v3.w, w3, a3.w);
    }
    for (; i < end; ++i) {
        int2 e = __ldg(reinterpret_cast<const int2*>(g_edge) + i);
        float w = __int_as_float(e.y);
        float4 v = ld_bf4(g_t + (size_t)e.x * D_OUT, sub);
        a0.x = fmaf(v.x, w, a0.x); a0.y = fmaf(v.y, w, a0.y);
        a0.z = fmaf(v.z, w, a0.z); a0.w = fmaf(v.w, w, a0.w);
    }
    a0.x += (a1.x + a2.x) + a3.x;
    a0.y += (a1.y + a2.y) + a3.y;
    a0.z += (a1.z + a2.z) + a3.z;
    a0.w += (a1.w + a2.w) + a3.w;
    float inv = 1.0f / fmaxf((float)(end - off), 1.0f);
    float4 rv = __ldg(reinterpret_cast<const float4*>(g_r + (size_t)n * D_OUT) + sub);
    a0.x = fmaf(a0.x, inv, rv.x);
    a0.y = fmaf(a0.y, inv, rv.y);
    a0.z = fmaf(a0.z, inv, rv.z);
    a0.w = fmaf(a0.w, inv, rv.w);
    reinterpret_cast<float4*>(out + (size_t)n * D_OUT)[sub] = a0;
}

// ---------------- launch ----------------
extern "C" void kernel_launch(void* const* d_in, const int* in_sizes, int n_in,
                              void* d_out, int out_size) {
    (void)in_sizes; (void)n_in;
    const float* x   = (const float*)d_in[0];
    const void*  ei  = d_in[1];                 // int32 or int64, detected on device
    const float* ew  = (const float*)d_in[2];
    const float* Wl1 = (const float*)d_in[3];
    const float* bl1 = (const float*)d_in[4];
    const float* Wr1 = (const float*)d_in[5];
    const float* Wl2 = (const float*)d_in[6];
    const float* bl2 = (const float*)d_in[7];
    const float* Wr2 = (const float*)d_in[8];

    float* hptr;
    float* lptr;
    const size_t full = (size_t)N_NODES * (D_HID + D_OUT);
    if ((size_t)out_size >= full) {
        hptr = (float*)d_out;
        lptr = hptr + (size_t)N_NODES * D_HID;
    } else {
        void* sym = nullptr;
        cudaGetSymbolAddress(&sym, g_h);
        hptr = (float*)sym;
        lptr = (float*)d_out;
    }

    int smcount = 148;
    if (cudaDeviceGetAttribute(&smcount, cudaDevAttrMultiProcessorCount, 0) != cudaSuccess)
        smcount = 148;

    cudaFuncSetAttribute(layer1_kernel,
                         cudaFuncAttributeMaxDynamicSharedMemorySize, L1_SMEM_BYTES);
    cudaFuncSetAttribute(tmat2_kernel,
                         cudaFuncAttributeMaxDynamicSharedMemorySize, T2_SMEM_BYTES);

    detect_zero_kernel<<<NBLK, 256>>>((const int*)ei);
    xcvt_kernel<<<4 * smcount, 256>>>(x);
    hist_kernel<<<N_EDGES / 256, 256>>>(ei);
    blocksum_kernel<<<NBLK, 256>>>();
    scan_bsum_kernel<<<1, 512>>>();
    offsets_kernel<<<NBLK, 256>>>();
    fill_kernel<<<N_EDGES / 256, 256>>>(ei, ew);
    gather1_kernel<<<(N_NODES * 32 + 255) / 256, 256>>>();
    layer1_kernel<<<smcount, 512, L1_SMEM_BYTES>>>(x, Wl1, bl1, Wr1, hptr);
    tmat2_kernel<<<2 * smcount, 512, T2_SMEM_BYTES>>>(hptr, Wl2, Wr2, bl2);
    gather2_kernel<<<(N_NODES * 16 + 255) / 256, 256>>>(lptr);
}

// round 10
// speedup vs baseline: 1.0805x; 1.0402x over previous
#include <cuda_runtime.h>
#include <cstddef>

#define N_NODES 100000
#define N_EDGES 3200000
#define D_IN    128
#define D_HID   128
#define D_OUT   64
#define NBLK    391           // ceil(N_NODES / 256)

// ---------------- scratch (no allocation allowed) ----------------
__device__ __align__(16) float g_agg1[(size_t)N_NODES * D_IN];   // mean-agg of x
__device__ __align__(16) float g_t   [(size_t)N_NODES * D_OUT];  // h @ W_l2^T
__device__ __align__(16) float g_r   [(size_t)N_NODES * D_OUT];  // h @ W_r2^T + b2
__device__ __align__(16) float g_h   [(size_t)N_NODES * D_HID];  // fallback h storage
__device__ int  g_deg [N_NODES];
__device__ int  g_off [N_NODES + 1];
__device__ int  g_pos [N_NODES];
__device__ int  g_bsum[NBLK];
__device__ __align__(16) int2 g_edge[N_EDGES];                   // (src, w-bits), dst-grouped
__device__ int  g_idx64;   // 1 if edge_index is int64, 0 if int32

// ---------------- f32x2 helpers ----------------
__device__ __forceinline__ unsigned long long ffma2(unsigned long long a,
                                                    unsigned long long b,
                                                    unsigned long long c) {
    unsigned long long d;
    asm("fma.rn.f32x2 %0, %1, %2, %3;" : "=l"(d) : "l"(a), "l"(b), "l"(c));
    return d;
}
__device__ __forceinline__ void unpack2(unsigned long long d, float& lo, float& hi) {
    asm("mov.b64 {%0, %1}, %2;" : "=f"(lo), "=f"(hi) : "l"(d));
}

// Load edge endpoint #e (src if half==0, dst if half==1) honoring detected dtype.
__device__ __forceinline__ int load_idx(const void* ei, int e, int half, int mode64) {
    if (mode64) {
        long long v = __ldg(reinterpret_cast<const long long*>(ei) +
                            (size_t)half * N_EDGES + e);
        return (int)v;
    } else {
        return __ldg(reinterpret_cast<const int*>(ei) + (size_t)half * N_EDGES + e);
    }
}

// ---------------- dtype detection + zero deg (merged) ----------------
__global__ void detect_zero_kernel(const int* __restrict__ ei_words) {
    int i = blockIdx.x * 256 + threadIdx.x;
    if (i < N_NODES) g_deg[i] = 0;
    if (blockIdx.x == 0) {
        __shared__ int any_nonzero;
        if (threadIdx.x == 0) any_nonzero = 0;
        __syncthreads();
        int acc = 0;
        for (int k = threadIdx.x; k < 4096; k += 256)
            acc |= ei_words[2 * k + 1];
        if (acc) atomicOr(&any_nonzero, 1);
        __syncthreads();
        if (threadIdx.x == 0) g_idx64 = any_nonzero ? 0 : 1;
    }
}

// ---------------- CSR build ----------------
__global__ void hist_kernel(const void* __restrict__ ei) {
    int e = blockIdx.x * blockDim.x + threadIdx.x;
    if (e >= N_EDGES) return;
    int mode64 = g_idx64;
    int d = load_idx(ei, e, 1, mode64);
    if ((unsigned)d < N_NODES) atomicAdd(&g_deg[d], 1);
}

__global__ void blocksum_kernel() {
    __shared__ int s[256];
    int i = blockIdx.x * 256 + threadIdx.x;
    s[threadIdx.x] = (i < N_NODES) ? g_deg[i] : 0;
    __syncthreads();
    for (int d = 128; d > 0; d >>= 1) {
        if (threadIdx.x < d) s[threadIdx.x] += s[threadIdx.x + d];
        __syncthreads();
    }
    if (threadIdx.x == 0) g_bsum[blockIdx.x] = s[0];
}

// merged: every block scans all NBLK block-sums in smem (391 ints), then
// scans its own 256 degrees. 512 threads.
__global__ void offsets_kernel() {
    __shared__ int bs[512];
    __shared__ int s[512];
    int t = threadIdx.x;
    // inclusive scan of block sums (padded to 512)
    int bv = (t < NBLK) ? g_bsum[t] : 0;
    bs[t] = bv;
    __syncthreads();
    for (int d = 1; d < 512; d <<= 1) {
        int tmp = (t >= d) ? bs[t - d] : 0;
        __syncthreads();
        bs[t] += tmp;
        __syncthreads();
    }
    int bpre = (blockIdx.x == 0) ? 0 : bs[blockIdx.x - 1];
    if (blockIdx.x == 0 && t == 0) g_off[N_NODES] = bs[NBLK - 1];
    // inclusive scan of this block's 256 degrees (entries 256..511 are zero)
    int i = blockIdx.x * 256 + t;      // only t<256 maps to a node
    int v = (t < 256 && i < N_NODES) ? g_deg[i] : 0;
    s[t] = v;
    __syncthreads();
    for (int d = 1; d < 512; d <<= 1) {
        int tmp = (t >= d) ? s[t - d] : 0;
        __syncthreads();
        s[t] += tmp;
        __syncthreads();
    }
    if (t < 256 && i < N_NODES) {
        int off = bpre + s[t] - v;     // exclusive
        g_off[i] = off;
        g_pos[i] = off;
    }
}

__global__ void fill_kernel(const void* __restrict__ ei,
                            const float* __restrict__ ew) {
    int e = blockIdx.x * blockDim.x + threadIdx.x;
    if (e >= N_EDGES) return;
    int mode64 = g_idx64;
    int s = load_idx(ei, e, 0, mode64);
    int d = load_idx(ei, e, 1, mode64);
    if ((unsigned)s >= N_NODES || (unsigned)d >= N_NODES) return;
    int p = atomicAdd(&g_pos[d], 1);
    g_edge[p] = make_int2(s, __float_as_int(__ldg(&ew[e])));
}

// ---------------- gather1: agg1[n] = mean over in-edges of x[src]*w ----------------
// one warp per node; lane covers 4 features (float4); batches of 4 with
// cross-batch edge prefetch (edge->data chain pipelined away)
__global__ void gather1_kernel(const float* __restrict__ x) {
    int n = (blockIdx.x * blockDim.x + threadIdx.x) >> 5;
    if (n >= N_NODES) return;
    int lane = threadIdx.x & 31;
    int off = g_off[n], end = g_off[n + 1];
    float4 a0 = make_float4(0.f, 0.f, 0.f, 0.f);
    float4 a1 = a0, a2 = a0, a3 = a0;
    int i = off;
    int2 e0, e1, e2, e3;
    bool have = (i + 4 <= end);
    if (have) {
        e0 = __ldg(reinterpret_cast<const int2*>(g_edge) + i + 0);
        e1 = __ldg(reinterpret_cast<const int2*>(g_edge) + i + 1);
        e2 = __ldg(reinterpret_cast<const int2*>(g_edge) + i + 2);
        e3 = __ldg(reinterpret_cast<const int2*>(g_edge) + i + 3);
    }
    for (; i + 8 <= end; i += 4) {
        // prefetch next batch's edges (independent of current data loads)
        int2 f0 = __ldg(reinterpret_cast<const int2*>(g_edge) + i + 4);
        int2 f1 = __ldg(reinterpret_cast<const int2*>(g_edge) + i + 5);
        int2 f2 = __ldg(reinterpret_cast<const int2*>(g_edge) + i + 6);
        int2 f3 = __ldg(reinterpret_cast<const int2*>(g_edge) + i + 7);
        float4 v0 = __ldg(reinterpret_cast<const float4*>(x + (size_t)e0.x * D_IN) + lane);
        float4 v1 = __ldg(reinterpret_cast<const float4*>(x + (size_t)e1.x * D_IN) + lane);
        float4 v2 = __ldg(reinterpret_cast<const float4*>(x + (size_t)e2.x * D_IN) + lane);
        float4 v3 = __ldg(reinterpret_cast<const float4*>(x + (size_t)e3.x * D_IN) + lane);
        float w0 = __int_as_float(e0.y), w1 = __int_as_float(e1.y);
        float w2 = __int_as_float(e2.y), w3 = __int_as_float(e3.y);
        a0.x = fmaf(v0.x, w0, a0.x); a0.y = fmaf(v0.y, w0, a0.y);
        a0.z = fmaf(v0.z, w0, a0.z); a0.w = fmaf(v0.w, w0, a0.w);
        a1.x = fmaf(v1.x, w1, a1.x); a1.y = fmaf(v1.y, w1, a1.y);
        a1.z = fmaf(v1.z, w1, a1.z); a1.w = fmaf(v1.w, w1, a1.w);
        a2.x = fmaf(v2.x, w2, a2.x); a2.y = fmaf(v2.y, w2, a2.y);
        a2.z = fmaf(v2.z, w2, a2.z); a2.w = fmaf(v2.w, w2, a2.w);
        a3.x = fmaf(v3.x, w3, a3.x); a3.y = fmaf(v3.y, w3, a3.y);
        a3.z = fmaf(v3.z, w3, a3.z); a3.w = fmaf(v3.w, w3, a3.w);
        e0 = f0; e1 = f1; e2 = f2; e3 = f3;
    }
    if (have) {
        // last full prefetched batch [i, i+4)
        float4 v0 = __ldg(reinterpret_cast<const float4*>(x + (size_t)e0.x * D_IN) + lane);
        float4 v1 = __ldg(reinterpret_cast<const float4*>(x + (size_t)e1.x * D_IN) + lane);
        float4 v2 = __ldg(reinterpret_cast<const float4*>(x + (size_t)e2.x * D_IN) + lane);
        float4 v3 = __ldg(reinterpret_cast<const float4*>(x + (size_t)e3.x * D_IN) + lane);
        float w0 = __int_as_float(e0.y), w1 = __int_as_float(e1.y);
        float w2 = __int_as_float(e2.y), w3 = __int_as_float(e3.y);
        a0.x = fmaf(v0.x, w0, a0.x); a0.y = fmaf(v0.y, w0, a0.y);
        a0.z = fmaf(v0.z, w0, a0.z); a0.w = fmaf(v0.w, w0, a0.w);
        a1.x = fmaf(v1.x, w1, a1.x); a1.y = fmaf(v1.y, w1, a1.y);
        a1.z = fmaf(v1.z, w1, a1.z); a1.w = fmaf(v1.w, w1, a1.w);
        a2.x = fmaf(v2.x, w2, a2.x); a2.y = fmaf(v2.y, w2, a2.y);
        a2.z = fmaf(v2.z, w2, a2.z); a2.w = fmaf(v2.w, w2, a2.w);
        a3.x = fmaf(v3.x, w3, a3.x); a3.y = fmaf(v3.y, w3, a3.y);
        a3.z = fmaf(v3.z, w3, a3.z); a3.w = fmaf(v3.w, w3, a3.w);
        i += 4;
    }
    for (; i < end; ++i) {
        int2 e = __ldg(reinterpret_cast<const int2*>(g_edge) + i);
        float w = __int_as_float(e.y);
        float4 v = __ldg(reinterpret_cast<const float4*>(x + (size_t)e.x * D_IN) + lane);
        a0.x = fmaf(v.x, w, a0.x); a0.y = fmaf(v.y, w, a0.y);
        a0.z = fmaf(v.z, w, a0.z); a0.w = fmaf(v.w, w, a0.w);
    }
    a0.x += (a1.x + a2.x) + a3.x;
    a0.y += (a1.y + a2.y) + a3.y;
    a0.z += (a1.z + a2.z) + a3.z;
    a0.w += (a1.w + a2.w) + a3.w;
    float inv = 1.0f / fmaxf((float)(end - off), 1.0f);
    a0.x *= inv; a0.y *= inv; a0.z *= inv; a0.w *= inv;
    reinterpret_cast<float4*>(g_agg1 + (size_t)n * D_IN)[lane] = a0;
}

// ---------------- layer 1 (f32x2, K-packed, 2ch x 8node blocking) -------------------
#define L1_WPAD 132
#define L1_TILE 64
#define L1_SMEM_BYTES (2 * 128 * L1_WPAD * 4 + 2 * L1_TILE * 128 * 4)  // 200704
__global__ void layer1_kernel(const float* __restrict__ x,
                              const float* __restrict__ Wl,
                              const float* __restrict__ bl,
                              const float* __restrict__ Wr,
                              float* __restrict__ hout) {
    extern __shared__ float sm[];
    float* wl = sm;                             // [128][132] native [j][k]
    float* wr = sm + 128 * L1_WPAD;
    float* fa = sm + 2 * 128 * L1_WPAD;         // [64][128]
    float* fx = fa + L1_TILE * 128;
    int t = threadIdx.x;
    for (int i = t; i < 128 * 128; i += 512) {
        int j = i >> 7, k = i & 127;
        wl[j * L1_WPAD + k] = Wl[i];
        wr[j * L1_WPAD + k] = Wr[i];
    }
    int j = t & 63;                             // channels j, j+64
    int grp = t >> 6;                           // 0..7 -> nodes grp*8 .. grp*8+7
    float bj0 = bl[j], bj1 = bl[j + 64];
    __syncthreads();
    const int NT = (N_NODES + L1_TILE - 1) / L1_TILE;   // 1563 (last tile partial)
    for (int tile = blockIdx.x; tile < NT; tile += gridDim.x) {
        int base = tile * L1_TILE;
        __syncthreads();
        for (int i = t; i < L1_TILE * 128; i += 512) {
            int n = i >> 7, k = i & 127;
            int node = base + n; if (node >= N_NODES) node = N_NODES - 1;
            fa[i] = g_agg1[(size_t)node * 128 + k];
            fx[i] = x[(size_t)node * 128 + k];
        }
        __syncthreads();
        unsigned long long acc0[8], acc1[8];
        #pragma unroll
        for (int n = 0; n < 8; ++n) { acc0[n] = 0ull; acc1[n] = 0ull; }
        const float* fan = fa + grp * 8 * 128;
        const float* fxn = fx + grp * 8 * 128;
        const float* wl0 = wl + j * L1_WPAD;
        const float* wl1 = wl + (j + 64) * L1_WPAD;
        const float* wr0 = wr + j * L1_WPAD;
        const float* wr1 = wr + (j + 64) * L1_WPAD;
        #pragma unroll 4
        for (int k = 0; k < 128; k += 4) {
            ulonglong2 wla = *reinterpret_cast<const ulonglong2*>(wl0 + k);
            ulonglong2 wlb = *reinterpret_cast<const ulonglong2*>(wl1 + k);
            ulonglong2 wra = *reinterpret_cast<const ulonglong2*>(wr0 + k);
            ulonglong2 wrb = *reinterpret_cast<const ulonglong2*>(wr1 + k);
            #pragma unroll
            for (int n = 0; n < 8; ++n) {
                ulonglong2 f_a = *reinterpret_cast<const ulonglong2*>(fan + n * 128 + k);
                ulonglong2 f_x = *reinterpret_cast<const ulonglong2*>(fxn + n * 128 + k);
                acc0[n] = ffma2(wla.x, f_a.x, acc0[n]);
                acc0[n] = ffma2(wla.y, f_a.y, acc0[n]);
                acc0[n] = ffma2(wra.x, f_x.x, acc0[n]);
                acc0[n] = ffma2(wra.y, f_x.y, acc0[n]);
                acc1[n] = ffma2(wlb.x, f_a.x, acc1[n]);
                acc1[n] = ffma2(wlb.y, f_a.y, acc1[n]);
                acc1[n] = ffma2(wrb.x, f_x.x, acc1[n]);
                acc1[n] = ffma2(wrb.y, f_x.y, acc1[n]);
            }
        }
        #pragma unroll
        for (int n = 0; n < 8; ++n) {
            int node = base + grp * 8 + n;
            if (node < N_NODES) {
                float lo, hi;
                unpack2(acc0[n], lo, hi);
                hout[(size_t)node * 128 + j] = fmaxf(lo + hi + bj0, 0.f);
                unpack2(acc1[n], lo, hi);
                hout[(size_t)node * 128 + j + 64] = fmaxf(lo + hi + bj1, 0.f);
            }
        }
    }
}

// ---------------- tmat2 (f32x2, K-packed, fused): t = h@Wl2^T ; r = h@Wr2^T + b2 --------
#define T2_WPAD 132
#define T2_TILE 32
#define T2_SMEM_BYTES (2 * 64 * T2_WPAD * 4 + T2_TILE * 128 * 4)  // 83968
__global__ void tmat2_kernel(const float* __restrict__ h,
                             const float* __restrict__ Wl2,
                             const float* __restrict__ Wr2,
                             const float* __restrict__ b2) {
    extern __shared__ float sm[];
    float* wl = sm;                             // [64][132] native [j][k]
    float* wr = sm + 64 * T2_WPAD;
    float* fh = sm + 2 * 64 * T2_WPAD;          // [32][128]
    int t = threadIdx.x;
    for (int i = t; i < 64 * 128; i += 512) {
        int j = i >> 7, k = i & 127;
        wl[j * T2_WPAD + k] = Wl2[i];
        wr[j * T2_WPAD + k] = Wr2[i];
    }
    int j = t & 63;
    int grp = t >> 6;                           // 0..7 -> nodes grp*4 .. grp*4+3
    float bj = b2[j];
    __syncthreads();
    const int NT = N_NODES / T2_TILE;           // 3125
    for (int tile = blockIdx.x; tile < NT; tile += gridDim.x) {
        int base = tile * T2_TILE;
        __syncthreads();
        for (int i = t; i < T2_TILE * 128; i += 512)
            fh[i] = h[(size_t)base * 128 + i];
        __syncthreads();
        unsigned long long tac[4], rac[4];
        #pragma unroll
        for (int n = 0; n < 4; ++n) { tac[n] = 0ull; rac[n] = 0ull; }
        const float* fn = fh + grp * 4 * 128;
        const float* wlj = wl + j * T2_WPAD;
        const float* wrj = wr + j * T2_WPAD;
        #pragma unroll 4
        for (int k = 0; k < 128; k += 4) {
            ulonglong2 w_l = *reinterpret_cast<const ulonglong2*>(wlj + k);
            ulonglong2 w_r = *reinterpret_cast<const ulonglong2*>(wrj + k);
            #pragma unroll
            for (int n = 0; n < 4; ++n) {
                ulonglong2 f = *reinterpret_cast<const ulonglong2*>(fn + n * 128 + k);
                tac[n] = ffma2(w_l.x, f.x, tac[n]);
                tac[n] = ffma2(w_l.y, f.y, tac[n]);
                rac[n] = ffma2(w_r.x, f.x, rac[n]);
                rac[n] = ffma2(w_r.y, f.y, rac[n]);
            }
        }
        #pragma unroll
        for (int n = 0; n < 4; ++n) {
            int node = base + grp * 4 + n;
            float lo, hi;
            unpack2(tac[n], lo, hi);
            g_t[(size_t)node * 64 + j] = lo + hi;
            unpack2(rac[n], lo, hi);
            g_r[(size_t)node * 64 + j] = lo + hi + bj;
        }
    }
}

// ---------------- gather2 + epilogue: out = mean-agg(t) + r ----------------
// HALF-warp per node (16 lanes x float4 = 64 ch); batches of 4 with edge prefetch
__global__ void gather2_kernel(float* __restrict__ out) {
    int gt = blockIdx.x * blockDim.x + threadIdx.x;
    int n = gt >> 4;
    if (n >= N_NODES) return;
    int sub = gt & 15;
    int off = g_off[n], end = g_off[n + 1];
    float4 a0 = make_float4(0.f, 0.f, 0.f, 0.f);
    float4 a1 = a0, a2 = a0, a3 = a0;
    int i = off;
    int2 e0, e1, e2, e3;
    bool have = (i + 4 <= end);
    if (have) {
        e0 = __ldg(reinterpret_cast<const int2*>(g_edge) + i + 0);
        e1 = __ldg(reinterpret_cast<const int2*>(g_edge) + i + 1);
        e2 = __ldg(reinterpret_cast<const int2*>(g_edge) + i + 2);
        e3 = __ldg(reinterpret_cast<const int2*>(g_edge) + i + 3);
    }
    for (; i + 8 <= end; i += 4) {
        int2 f0 = __ldg(reinterpret_cast<const int2*>(g_edge) + i + 4);
        int2 f1 = __ldg(reinterpret_cast<const int2*>(g_edge) + i + 5);
        int2 f2 = __ldg(reinterpret_cast<const int2*>(g_edge) + i + 6);
        int2 f3 = __ldg(reinterpret_cast<const int2*>(g_edge) + i + 7);
        float4 v0 = __ldg(reinterpret_cast<const float4*>(g_t + (size_t)e0.x * D_OUT) + sub);
        float4 v1 = __ldg(reinterpret_cast<const float4*>(g_t + (size_t)e1.x * D_OUT) + sub);
        float4 v2 = __ldg(reinterpret_cast<const float4*>(g_t + (size_t)e2.x * D_OUT) + sub);
        float4 v3 = __ldg(reinterpret_cast<const float4*>(g_t + (size_t)e3.x * D_OUT) + sub);
        float w0 = __int_as_float(e0.y), w1 = __int_as_float(e1.y);
        float w2 = __int_as_float(e2.y), w3 = __int_as_float(e3.y);
        a0.x = fmaf(v0.x, w0, a0.x); a0.y = fmaf(v0.y, w0, a0.y);
        a0.z = fmaf(v0.z, w0, a0.z); a0.w = fmaf(v0.w, w0, a0.w);
        a1.x = fmaf(v1.x, w1, a1.x); a1.y = fmaf(v1.y, w1, a1.y);
        a1.z = fmaf(v1.z, w1, a1.z); a1.w = fmaf(v1.w, w1, a1.w);
        a2.x = fmaf(v2.x, w2, a2.x); a2.y = fmaf(v2.y, w2, a2.y);
        a2.z = fmaf(v2.z, w2, a2.z); a2.w = fmaf(v2.w, w2, a2.w);
        a3.x = fmaf(v3.x, w3, a3.x); a3.y = fmaf(v3.y, w3, a3.y);
        a3.z = fmaf(v3.z, w3, a3.z); a3.w = fmaf(v3.w, w3, a3.w);
        e0 = f0; e1 = f1; e2 = f2; e3 = f3;
    }
    if (have) {
        float4 v0 = __ldg(reinterpret_cast<const float4*>(g_t + (size_t)e0.x * D_OUT) + sub);
        float4 v1 = __ldg(reinterpret_cast<const float4*>(g_t + (size_t)e1.x * D_OUT) + sub);
        float4 v2 = __ldg(reinterpret_cast<const float4*>(g_t + (size_t)e2.x * D_OUT) + sub);
        float4 v3 = __ldg(reinterpret_cast<const float4*>(g_t + (size_t)e3.x * D_OUT) + sub);
        float w0 = __int_as_float(e0.y), w1 = __int_as_float(e1.y);
        float w2 = __int_as_float(e2.y), w3 = __int_as_float(e3.y);
        a0.x = fmaf(v0.x, w0, a0.x); a0.y = fmaf(v0.y, w0, a0.y);
        a0.z = fmaf(v0.z, w0, a0.z); a0.w = fmaf(v0.w, w0, a0.w);
        a1.x = fmaf(v1.x, w1, a1.x); a1.y = fmaf(v1.y, w1, a1.y);
        a1.z = fmaf(v1.z, w1, a1.z); a1.w = fmaf(v1.w, w1, a1.w);
        a2.x = fmaf(v2.x, w2, a2.x); a2.y = fmaf(v2.y, w2, a2.y);
        a2.z = fmaf(v2.z, w2, a2.z); a2.w = fmaf(v2.w, w2, a2.w);
        a3.x = fmaf(v3.x, w3, a3.x); a3.y = fmaf(v3.y, w3, a3.y);
        a3.z = fmaf(v3.z, w3, a3.z); a3.w = fmaf(v3.w, w3, a3.w);
        i += 4;
    }
    for (; i < end; ++i) {
        int2 e = __ldg(reinterpret_cast<const int2*>(g_edge) + i);
        float w = __int_as_float(e.y);
        float4 v = __ldg(reinterpret_cast<const float4*>(g_t + (size_t)e.x * D_OUT) + sub);
        a0.x = fmaf(v.x, w, a0.x); a0.y = fmaf(v.y, w, a0.y);
        a0.z = fmaf(v.z, w, a0.z); a0.w = fmaf(v.w, w, a0.w);
    }
    a0.x += (a1.x + a2.x) + a3.x;
    a0.y += (a1.y + a2.y) + a3.y;
    a0.z += (a1.z + a2.z) + a3.z;
    a0.w += (a1.w + a2.w) + a3.w;
    float inv = 1.0f / fmaxf((float)(end - off), 1.0f);
    float4 rv = __ldg(reinterpret_cast<const float4*>(g_r + (size_t)n * D_OUT) + sub);
    a0.x = fmaf(a0.x, inv, rv.x);
    a0.y = fmaf(a0.y, inv, rv.y);
    a0.z = fmaf(a0.z, inv, rv.z);
    a0.w = fmaf(a0.w, inv, rv.w);
    reinterpret_cast<float4*>(out + (size_t)n * D_OUT)[sub] = a0;
}

// ---------------- launch ----------------
extern "C" void kernel_launch(void* const* d_in, const int* in_sizes, int n_in,
                              void* d_out, int out_size) {
    (void)in_sizes; (void)n_in;
    const float* x   = (const float*)d_in[0];
    const void*  ei  = d_in[1];                 // int32 or int64, detected on device
    const float* ew  = (const float*)d_in[2];
    const float* Wl1 = (const float*)d_in[3];
    const float* bl1 = (const float*)d_in[4];
    const float* Wr1 = (const float*)d_in[5];
    const float* Wl2 = (const float*)d_in[6];
    const float* bl2 = (const float*)d_in[7];
    const float* Wr2 = (const float*)d_in[8];

    float* hptr;
    float* lptr;
    const size_t full = (size_t)N_NODES * (D_HID + D_OUT);
    if ((size_t)out_size >= full) {
        hptr = (float*)d_out;
        lptr = hptr + (size_t)N_NODES * D_HID;
    } else {
        void* sym = nullptr;
        cudaGetSymbolAddress(&sym, g_h);
        hptr = (float*)sym;
        lptr = (float*)d_out;
    }

    int smcount = 148;
    if (cudaDeviceGetAttribute(&smcount, cudaDevAttrMultiProcessorCount, 0) != cudaSuccess)
        smcount = 148;

    cudaFuncSetAttribute(layer1_kernel,
                         cudaFuncAttributeMaxDynamicSharedMemorySize, L1_SMEM_BYTES);
    cudaFuncSetAttribute(tmat2_kernel,
                         cudaFuncAttributeMaxDynamicSharedMemorySize, T2_SMEM_BYTES);

    detect_zero_kernel<<<NBLK, 256>>>((const int*)ei);     // 1
    hist_kernel<<<N_EDGES / 256, 256>>>(ei);               // 2
    blocksum_kernel<<<NBLK, 256>>>();                      // 3
    offsets_kernel<<<NBLK, 512>>>();                       // 4 (merged scan)
    fill_kernel<<<N_EDGES / 256, 256>>>(ei, ew);           // 5
    gather1_kernel<<<(N_NODES * 32 + 255) / 256, 256>>>(x);// 6 <- ncu -s 5 -c 1 target
    layer1_kernel<<<smcount, 512, L1_SMEM_BYTES>>>(x, Wl1, bl1, Wr1, hptr);
    tmat2_kernel<<<2 * smcount, 512, T2_SMEM_BYTES>>>(hptr, Wl2, Wr2, bl2);
    gather2_kernel<<<(N_NODES * 16 + 255) / 256, 256>>>(lptr);
}